// round 16
// baseline (speedup 1.0000x reference)
#include <cuda_runtime.h>
#include <cuda_fp16.h>
#include <cstdint>

// Problem constants
#define BATCH   2
#define S_LEN   2048
#define D_MODEL 768
#define N_HEADS 12
#define HEAD_D  64
#define M_ROWS  (BATCH * S_LEN)   // 4096

// ---------------------------------------------------------------------------
// Scratch (no allocations allowed -> __device__ globals). fp16 everywhere.
// ---------------------------------------------------------------------------
__device__ __half g_q[M_ROWS * D_MODEL];
__device__ __half g_k[M_ROWS * D_MODEL];
__device__ __half g_v[M_ROWS * D_MODEL];
__device__ __half g_att[M_ROWS * D_MODEL];
__device__ __half g_xh[M_ROWS * D_MODEL];
__device__ __half g_wq[D_MODEL * D_MODEL];
__device__ __half g_wk[D_MODEL * D_MODEL];
__device__ __half g_wv[D_MODEL * D_MODEL];
__device__ __half g_wo[D_MODEL * D_MODEL];

// ---------------------------------------------------------------------------
// mma / ldmatrix / cp.async helpers
// ---------------------------------------------------------------------------
__device__ __forceinline__ void mma16(float c[4], const unsigned a[4],
                                      const unsigned b[2]) {
    asm volatile(
        "mma.sync.aligned.m16n8k16.row.col.f32.f16.f16.f32 "
        "{%0,%1,%2,%3}, {%4,%5,%6,%7}, {%8,%9}, {%0,%1,%2,%3};"
        : "+f"(c[0]), "+f"(c[1]), "+f"(c[2]), "+f"(c[3])
        : "r"(a[0]), "r"(a[1]), "r"(a[2]), "r"(a[3]),
          "r"(b[0]), "r"(b[1]));
}

__device__ __forceinline__ void ldsm_x4(unsigned& r0, unsigned& r1,
                                        unsigned& r2, unsigned& r3,
                                        const __half* p) {
    uint32_t a = (uint32_t)__cvta_generic_to_shared(p);
    asm volatile("ldmatrix.sync.aligned.m8n8.x4.shared.b16 {%0,%1,%2,%3}, [%4];"
                 : "=r"(r0), "=r"(r1), "=r"(r2), "=r"(r3) : "r"(a));
}

__device__ __forceinline__ void ldsm_x4t(unsigned& r0, unsigned& r1,
                                         unsigned& r2, unsigned& r3,
                                         const __half* p) {
    uint32_t a = (uint32_t)__cvta_generic_to_shared(p);
    asm volatile("ldmatrix.sync.aligned.m8n8.x4.trans.shared.b16 {%0,%1,%2,%3}, [%4];"
                 : "=r"(r0), "=r"(r1), "=r"(r2), "=r"(r3) : "r"(a));
}

__device__ __forceinline__ void cp_async16(__half* dst, const __half* src) {
    uint32_t d = (uint32_t)__cvta_generic_to_shared(dst);
    asm volatile("cp.async.cg.shared.global [%0], [%1], 16;" :: "r"(d), "l"(src));
}
#define CP_COMMIT() asm volatile("cp.async.commit_group;" ::: "memory")
template <int N>
__device__ __forceinline__ void cp_wait() {
    asm volatile("cp.async.wait_group %0;" :: "n"(N) : "memory");
}

__device__ __forceinline__ unsigned ex2_f16x2(unsigned x) {
    unsigned r;
    asm("ex2.approx.f16x2 %0, %1;" : "=r"(r) : "r"(x));
    return r;
}

__device__ __forceinline__ void st2(float* p, float a, float b) {
    *(float2*)p = make_float2(a, b);
}
__device__ __forceinline__ void st2(__half* p, float a, float b) {
    *(__half2*)p = __floats2half2_rn(a, b);
}

// ---------------------------------------------------------------------------
// One-shot fp32 -> fp16 conversion of x and the four weight matrices.
// ---------------------------------------------------------------------------
__global__ __launch_bounds__(256)
void cvt_all(const float* __restrict__ x,
             const float* __restrict__ wq, const float* __restrict__ wk,
             const float* __restrict__ wv, const float* __restrict__ wo) {
    const float* src; __half* dst; size_t off;
    const int bx = blockIdx.x;
    if (bx < 1536)      { src = x;  dst = g_xh; off = (size_t)bx * 2048; }
    else if (bx < 1824) { src = wq; dst = g_wq; off = (size_t)(bx - 1536) * 2048; }
    else if (bx < 2112) { src = wk; dst = g_wk; off = (size_t)(bx - 1824) * 2048; }
    else if (bx < 2400) { src = wv; dst = g_wv; off = (size_t)(bx - 2112) * 2048; }
    else                { src = wo; dst = g_wo; off = (size_t)(bx - 2400) * 2048; }
    off += (size_t)threadIdx.x * 8;
    float4 a = *(const float4*)(src + off);
    float4 b = *(const float4*)(src + off + 4);
    __half2* d = (__half2*)(dst + off);
    d[0] = __floats2half2_rn(a.x, a.y);
    d[1] = __floats2half2_rn(a.z, a.w);
    d[2] = __floats2half2_rn(b.x, b.y);
    d[3] = __floats2half2_rn(b.z, b.w);
}

// ---------------------------------------------------------------------------
// GEMM: C[4096,768] = A[4096,768] @ W[768,768] + bias (optionally * scale).
// Block 256x128, 512 threads, 16 warps (4m x 4n), warp tile 64x32.
// BK=64 (12 k-tiles), 3-stage cp.async pipeline, one sync per tile:
//   iter t: wait<1> (tile t resident) -> sync (all warps done with t-1's
//   buffer) -> issue fill t+2 into (t+2)%3 == (t-1)%3 -> compute t.
// Dynamic smem: 3*(256*72 + 64*136)*2 = 162816 B -> 1 CTA/SM.
// ---------------------------------------------------------------------------
#define AP_G 72
#define WP_G 136
#define KTILES (D_MODEL / 64)   // 12
#define GEMM_SMEM ((3 * 256 * AP_G + 3 * 64 * WP_G) * (int)sizeof(__half))

template <typename TOUT>
__device__ __forceinline__
void gemm_body(const __half* __restrict__ A, const __half* __restrict__ W,
               const float* __restrict__ bias, TOUT* __restrict__ C,
               float scale) {
    extern __shared__ __half dynsm[];
    __half* As = dynsm;                  // [3][256*AP_G]
    __half* Ws = dynsm + 3 * 256 * AP_G; // [3][64*WP_G]

    const int tid  = threadIdx.x;
    const int lane = tid & 31, wid = tid >> 5;
    const int gid  = lane >> 2, tig = lane & 3;
    const int wm   = (wid >> 2) * 64;    // 0..192
    const int wn   = (wid & 3) * 32;     // 0..96
    const int row0 = blockIdx.y * 256;
    const int col0 = blockIdx.x * 128;

    float acc[4][4][4];
#pragma unroll
    for (int mi = 0; mi < 4; mi++)
#pragma unroll
        for (int ni = 0; ni < 4; ni++)
#pragma unroll
            for (int j = 0; j < 4; j++) acc[mi][ni][j] = 0.f;

    // A tile 256x64 halves = 2048 16B chunks (4/thread);
    // W tile 64x128 = 1024 chunks (2/thread).
#define FILL_ASYNC(bf, k0)                                                     \
    {                                                                          \
        __half* ad = As + (bf) * 256 * AP_G;                                   \
        __half* wd = Ws + (bf) * 64 * WP_G;                                    \
        _Pragma("unroll")                                                      \
        for (int j = 0; j < 4; j++) {                                          \
            const int ch = tid + 512 * j;                                      \
            const int r = ch >> 3, c8 = (ch & 7) << 3;                         \
            cp_async16(&ad[r * AP_G + c8],                                     \
                       A + (size_t)(row0 + r) * D_MODEL + (k0) + c8);          \
        }                                                                      \
        _Pragma("unroll")                                                      \
        for (int j = 0; j < 2; j++) {                                          \
            const int ch = tid + 512 * j;                                      \
            const int r = ch >> 4, c8 = (ch & 15) << 3;                        \
            cp_async16(&wd[r * WP_G + c8],                                     \
                       W + (size_t)((k0) + r) * D_MODEL + col0 + c8);          \
        }                                                                      \
    }

    FILL_ASYNC(0, 0);
    CP_COMMIT();
    FILL_ASYNC(1, 64);
    CP_COMMIT();

    for (int t = 0; t < KTILES; t++) {
        const int buf = t % 3;
        if (t < KTILES - 1) cp_wait<1>(); else cp_wait<0>();
        __syncthreads();     // all warps done reading buffer (t-1)%3
        if (t < KTILES - 2) {
            FILL_ASYNC((t + 2) % 3, (t + 2) * 64);
            CP_COMMIT();
        }
        const __half* ab = As + buf * 256 * AP_G;
        const __half* wb = Ws + buf * 64 * WP_G;

#pragma unroll
        for (int ks = 0; ks < 4; ks++) {
            const int kk = ks * 16;
            unsigned a[4][4];
#pragma unroll
            for (int mi = 0; mi < 4; mi++)
                ldsm_x4(a[mi][0], a[mi][1], a[mi][2], a[mi][3],
                        &ab[(wm + mi * 16 + (lane & 15)) * AP_G +
                            kk + (lane >> 4) * 8]);
#pragma unroll
            for (int nip = 0; nip < 2; nip++) {
                unsigned r0, r1, r2, r3;
                ldsm_x4t(r0, r1, r2, r3,
                         &wb[(kk + (lane & 15)) * WP_G +
                             wn + nip * 16 + (lane >> 4) * 8]);
                unsigned b0[2] = {r0, r1}, b1[2] = {r2, r3};
#pragma unroll
                for (int mi = 0; mi < 4; mi++) {
                    mma16(acc[mi][2 * nip],     a[mi], b0);
                    mma16(acc[mi][2 * nip + 1], a[mi], b1);
                }
            }
        }
    }
#undef FILL_ASYNC

    // epilogue: (acc + bias) * scale, paired stores
#pragma unroll
    for (int mi = 0; mi < 4; mi++) {
        const int r = row0 + wm + mi * 16 + gid;
#pragma unroll
        for (int ni = 0; ni < 4; ni++) {
            const int c = col0 + wn + 8 * ni + 2 * tig;
            const float b0 = bias[c], b1 = bias[c + 1];
            st2(C + (size_t)r * D_MODEL + c,
                (acc[mi][ni][0] + b0) * scale, (acc[mi][ni][1] + b1) * scale);
            st2(C + (size_t)(r + 8) * D_MODEL + c,
                (acc[mi][ni][2] + b0) * scale, (acc[mi][ni][3] + b1) * scale);
        }
    }
}

// Fused QKV projection. Q output pre-scaled by 1/sqrt(64) = 0.125.
__global__ __launch_bounds__(512)
void qkv_gemm(const float* __restrict__ bq, const float* __restrict__ bk,
              const float* __restrict__ bv) {
    if (blockIdx.z == 0)
        gemm_body<__half>(g_xh, g_wq, bq, g_q, 0.125f);
    else if (blockIdx.z == 1)
        gemm_body<__half>(g_xh, g_wk, bk, g_k, 1.0f);
    else
        gemm_body<__half>(g_xh, g_wv, bv, g_v, 1.0f);
}

__global__ __launch_bounds__(512)
void o_gemm(const float* __restrict__ bias, float* __restrict__ out) {
    gemm_body<float>(g_att, g_wo, bias, out, 1.0f);
}

// ---------------------------------------------------------------------------
// Flash attention, fp16 mma, register-resident softmax, ex2.f16x2 exp.
// NEW: Q fragments hoisted to registers once (Q is kv-tile-invariant), and
// 3-stage KV cp.async pipeline with one sync per tile:
//   iter t: wait<1> -> sync -> issue fill t+2 -> compute t.
// Smem: Q [128][72] + 3x2x[64][72] = 73728 B -> 2 CTAs/SM.
// ---------------------------------------------------------------------------
#define QP 72
#define KP 72
#define ATT_SMEM ((128 * QP + 3 * 2 * 64 * KP) * (int)sizeof(__half))

__global__ __launch_bounds__(256)
void attn_f16(const __half* __restrict__ Q, const __half* __restrict__ K,
              const __half* __restrict__ V, __half* __restrict__ O) {
    extern __shared__ __half sh[];
    __half* Qs = sh;                   // [128][QP]
    __half* Ks = Qs + 128 * QP;        // [3][64*KP]
    __half* Vs = Ks + 3 * 64 * KP;     // [3][64*KP]

    const int tid  = threadIdx.x;
    const int lane = tid & 31, wid = tid >> 5;
    const int gid  = lane >> 2, tig = lane & 3;
    const int wm   = wid * 16;
    const int b    = blockIdx.z, h = blockIdx.y;
    const int q0   = blockIdx.x * 128;

    const __half* qb = Q + ((size_t)(b * S_LEN + q0)) * D_MODEL + h * HEAD_D;
    const __half* kb = K + ((size_t)b * S_LEN) * D_MODEL + h * HEAD_D;
    const __half* vb = V + ((size_t)b * S_LEN) * D_MODEL + h * HEAD_D;

    // Q fill: 128x64 halves = 1024 x 16B chunks (goes into group 0)
#pragma unroll
    for (int j = 0; j < 4; j++) {
        const int ch = tid + 256 * j;
        const int r = ch >> 3, c8 = (ch & 7) << 3;
        cp_async16(&Qs[r * QP + c8], qb + (size_t)r * D_MODEL + c8);
    }

#define FILL_KV_ASYNC(bf, kt)                                                  \
    {                                                                          \
        __half* kd = &Ks[(bf) * 64 * KP];                                      \
        __half* vd = &Vs[(bf) * 64 * KP];                                      \
        _Pragma("unroll")                                                      \
        for (int jj = 0; jj < 2; jj++) {                                       \
            const int ch = tid + 256 * jj;                                     \
            const int r = ch >> 3, c8 = (ch & 7) << 3;                         \
            cp_async16(&kd[r * KP + c8],                                       \
                       kb + (size_t)((kt) + r) * D_MODEL + c8);                \
            cp_async16(&vd[r * KP + c8],                                       \
                       vb + (size_t)((kt) + r) * D_MODEL + c8);                \
        }                                                                      \
    }

    float m0 = -1e30f, m1 = -1e30f, l0 = 0.f, l1 = 0.f;
    float oa[8][4];
#pragma unroll
    for (int ni = 0; ni < 8; ni++)
#pragma unroll
        for (int j = 0; j < 4; j++) oa[ni][j] = 0.f;

    FILL_KV_ASYNC(0, 0);
    CP_COMMIT();            // group 0 = {Q, K0, V0}
    FILL_KV_ASYNC(1, 64);
    CP_COMMIT();            // group 1 = {K1, V1}

    // Hoist Q fragments: group 0 done once <=1 group pending.
    cp_wait<1>();
    __syncthreads();
    unsigned qf[4][4];
#pragma unroll
    for (int s = 0; s < 4; s++)
        ldsm_x4(qf[s][0], qf[s][1], qf[s][2], qf[s][3],
                &Qs[(wm + (lane & 15)) * QP + 16 * s + (lane >> 4) * 8]);

    const int NT = S_LEN / 64;   // 32
    for (int t = 0; t < NT; ++t) {
        const int buf = t % 3;
        if (t < NT - 1) cp_wait<1>(); else cp_wait<0>();
        __syncthreads();     // all warps done reading buffer (t-1)%3
        if (t < NT - 2) {
            FILL_KV_ASYNC((t + 2) % 3, (t + 2) * 64);
            CP_COMMIT();
        }

        const __half* kbuf = &Ks[buf * 64 * KP];
        const __half* vbuf = &Vs[buf * 64 * KP];

        // --- S = Q @ K^T : rows wm..wm+15, all 64 kv cols, accum fp32
        float sf[8][4];
#pragma unroll
        for (int ni = 0; ni < 8; ni++)
#pragma unroll
            for (int j = 0; j < 4; j++) sf[ni][j] = 0.f;

#pragma unroll
        for (int s = 0; s < 4; s++) {
#pragma unroll
            for (int nip = 0; nip < 4; nip++) {
                unsigned r0, r1, r2, r3;
                ldsm_x4(r0, r1, r2, r3,
                        &kbuf[(nip * 16 + (lane & 7) + ((lane >> 4) & 1) * 8) * KP +
                              16 * s + ((lane >> 3) & 1) * 8]);
                unsigned bb0[2] = {r0, r1}, bb1[2] = {r2, r3};
                mma16(sf[2 * nip],     qf[s], bb0);
                mma16(sf[2 * nip + 1], qf[s], bb1);
            }
        }

        // --- register-resident online softmax (rows gid and gid+8)
        float mx0 = sf[0][0], mx1 = sf[0][2];
#pragma unroll
        for (int ni = 0; ni < 8; ni++) {
            mx0 = fmaxf(mx0, fmaxf(sf[ni][0], sf[ni][1]));
            mx1 = fmaxf(mx1, fmaxf(sf[ni][2], sf[ni][3]));
        }
        mx0 = fmaxf(mx0, __shfl_xor_sync(0xffffffffu, mx0, 1));
        mx0 = fmaxf(mx0, __shfl_xor_sync(0xffffffffu, mx0, 2));
        mx1 = fmaxf(mx1, __shfl_xor_sync(0xffffffffu, mx1, 1));
        mx1 = fmaxf(mx1, __shfl_xor_sync(0xffffffffu, mx1, 2));
        const float nm0 = fmaxf(m0, mx0), nm1 = fmaxf(m1, mx1);
        const float al0 = __expf(m0 - nm0), al1 = __expf(m1 - nm1);
        m0 = nm0; m1 = nm1;

        const float L2E = 1.44269504f;
        const float base0 = m0 * L2E, base1 = m1 * L2E;
        unsigned ph0[8], ph1[8];
        float s0 = 0.f, s1 = 0.f;
#pragma unroll
        for (int ni = 0; ni < 8; ni++) {
            __half2 a0 = __floats2half2_rn(fmaf(sf[ni][0], L2E, -base0),
                                           fmaf(sf[ni][1], L2E, -base0));
            __half2 a1 = __floats2half2_rn(fmaf(sf[ni][2], L2E, -base1),
                                           fmaf(sf[ni][3], L2E, -base1));
            ph0[ni] = ex2_f16x2(*(unsigned*)&a0);
            ph1[ni] = ex2_f16x2(*(unsigned*)&a1);
            float2 f0 = __half22float2(*(__half2*)&ph0[ni]);
            float2 f1 = __half22float2(*(__half2*)&ph1[ni]);
            s0 += f0.x + f0.y;
            s1 += f1.x + f1.y;
        }
        s0 += __shfl_xor_sync(0xffffffffu, s0, 1);
        s0 += __shfl_xor_sync(0xffffffffu, s0, 2);
        s1 += __shfl_xor_sync(0xffffffffu, s1, 1);
        s1 += __shfl_xor_sync(0xffffffffu, s1, 2);
        l0 = l0 * al0 + s0;
        l1 = l1 * al1 + s1;

#pragma unroll
        for (int ni = 0; ni < 8; ni++) {
            oa[ni][0] *= al0; oa[ni][1] *= al0;
            oa[ni][2] *= al1; oa[ni][3] *= al1;
        }

        // --- O += P @ V : A = P (regs), B = V via ldmatrix.trans
#pragma unroll
        for (int s = 0; s < 4; s++) {
            unsigned a[4] = {ph0[2 * s], ph1[2 * s],
                             ph0[2 * s + 1], ph1[2 * s + 1]};
#pragma unroll
            for (int nip = 0; nip < 4; nip++) {
                unsigned r0, r1, r2, r3;
                ldsm_x4t(r0, r1, r2, r3,
                         &vbuf[(16 * s + (lane & 15)) * KP +
                               nip * 16 + (lane >> 4) * 8]);
                unsigned bb0[2] = {r0, r1}, bb1[2] = {r2, r3};
                mma16(oa[2 * nip],     a, bb0);
                mma16(oa[2 * nip + 1], a, bb1);
            }
        }
    }
#undef FILL_KV_ASYNC

    // --- epilogue: normalize, write [b, q, h*64 + d] as fp16
    __half* ob = O + ((size_t)(b * S_LEN + q0)) * D_MODEL + h * HEAD_D;
    const float li0 = 1.f / l0, li1 = 1.f / l1;
#pragma unroll
    for (int ni = 0; ni < 8; ni++) {
        const int c = 8 * ni + 2 * tig;
        *(__half2*)(ob + (size_t)(wm + gid) * D_MODEL + c) =
            __floats2half2_rn(oa[ni][0] * li0, oa[ni][1] * li0);
        *(__half2*)(ob + (size_t)(wm + gid + 8) * D_MODEL + c) =
            __floats2half2_rn(oa[ni][2] * li1, oa[ni][3] * li1);
    }
}

// ---------------------------------------------------------------------------
// Launch
// ---------------------------------------------------------------------------
extern "C" void kernel_launch(void* const* d_in, const int* in_sizes, int n_in,
                              void* d_out, int out_size) {
    const float* x  = (const float*)d_in[0];
    const float* Wq = (const float*)d_in[1];
    const float* bq = (const float*)d_in[2];
    const float* Wk = (const float*)d_in[3];
    const float* bk = (const float*)d_in[4];
    const float* Wv = (const float*)d_in[5];
    const float* bv = (const float*)d_in[6];
    const float* Wo = (const float*)d_in[7];
    const float* bo = (const float*)d_in[8];
    float* out = (float*)d_out;

    void *qp, *kp, *vp, *ap;
    cudaGetSymbolAddress(&qp, g_q);
    cudaGetSymbolAddress(&kp, g_k);
    cudaGetSymbolAddress(&vp, g_v);
    cudaGetSymbolAddress(&ap, g_att);

    cudaFuncSetAttribute(attn_f16,
                         cudaFuncAttributeMaxDynamicSharedMemorySize, ATT_SMEM);
    cudaFuncSetAttribute(qkv_gemm,
                         cudaFuncAttributeMaxDynamicSharedMemorySize, GEMM_SMEM);
    cudaFuncSetAttribute(o_gemm,
                         cudaFuncAttributeMaxDynamicSharedMemorySize, GEMM_SMEM);

    // fp32 -> fp16 conversion of x + all weights (2688 blocks)
    cvt_all<<<2688, 256>>>(x, Wq, Wk, Wv, Wo);

    dim3 qkv_grid(D_MODEL / 128, M_ROWS / 256, 3);   // (6, 16, 3) = 288
    qkv_gemm<<<qkv_grid, 512, GEMM_SMEM>>>(bq, bk, bv);

    dim3 attn_grid(S_LEN / 128, N_HEADS, BATCH);     // (16, 12, 2) = 384
    attn_f16<<<attn_grid, 256, ATT_SMEM>>>((const __half*)qp,
                                           (const __half*)kp,
                                           (const __half*)vp,
                                           (__half*)ap);

    dim3 o_grid(D_MODEL / 128, M_ROWS / 256);        // (6, 16) = 96
    o_gemm<<<o_grid, 512, GEMM_SMEM>>>(bo, out);
}